// round 1
// baseline (speedup 1.0000x reference)
#include <cuda_runtime.h>

#define BT 192
#define NN 512
#define FF 64
#define NEG_INF_F (-9000000000000000.0f)
#define ALPHA_F 0.2f

// Scratch (device globals — no allocation allowed)
__device__ float g_Wh[BT * NN * FF];     // 25 MB
__device__ float g_Wh1[BT * NN];
__device__ float g_Wh2[BT * NN];

// ---------------------------------------------------------------------------
// Kernel 1: Wh = h @ W, fused Wh1 = Wh@a1, Wh2 = Wh@a2.
// Block: 128 threads, 32 nodes x 64 outputs, thread tile 4x4.
// ---------------------------------------------------------------------------
__global__ __launch_bounds__(128) void wh_kernel(const float* __restrict__ h,
                                                 const float* __restrict__ W,
                                                 const float* __restrict__ a) {
    __shared__ float Ws[FF * FF];       // 16 KB
    __shared__ float hs[32][68];        // padded stride to dodge bank conflicts

    int tid = threadIdx.x;
    int node0 = blockIdx.x * 32;        // grid = (BT*NN)/32 = 3072

    // Stage W (64x64) into smem, float4 coalesced
    const float4* W4 = (const float4*)W;
    float4* Ws4 = (float4*)Ws;
    #pragma unroll
    for (int k = tid; k < FF * FF / 4; k += 128) Ws4[k] = W4[k];

    // Stage h tile (32x64)
    #pragma unroll
    for (int k = tid; k < 32 * FF / 4; k += 128) {
        int n = k >> 4, c = k & 15;
        float4 v = ((const float4*)(h + (size_t)(node0 + n) * FF))[c];
        hs[n][c * 4 + 0] = v.x; hs[n][c * 4 + 1] = v.y;
        hs[n][c * 4 + 2] = v.z; hs[n][c * 4 + 3] = v.w;
    }
    __syncthreads();

    int ot = tid & 15;   // output group: o base = ot*4
    int nt = tid >> 4;   // node group:  n base = nt*4
    int ob = ot * 4, nb = nt * 4;

    float acc[4][4];
    #pragma unroll
    for (int i = 0; i < 4; i++)
        #pragma unroll
        for (int j = 0; j < 4; j++) acc[i][j] = 0.f;

    #pragma unroll 8
    for (int f = 0; f < FF; f++) {
        float4 w = *(const float4*)&Ws[f * FF + ob];
        float h0 = hs[nb + 0][f], h1 = hs[nb + 1][f];
        float h2 = hs[nb + 2][f], h3 = hs[nb + 3][f];
        acc[0][0] += h0 * w.x; acc[0][1] += h0 * w.y; acc[0][2] += h0 * w.z; acc[0][3] += h0 * w.w;
        acc[1][0] += h1 * w.x; acc[1][1] += h1 * w.y; acc[1][2] += h1 * w.z; acc[1][3] += h1 * w.w;
        acc[2][0] += h2 * w.x; acc[2][1] += h2 * w.y; acc[2][2] += h2 * w.z; acc[2][3] += h2 * w.w;
        acc[3][0] += h3 * w.x; acc[3][1] += h3 * w.y; acc[3][2] += h3 * w.z; acc[3][3] += h3 * w.w;
    }

    // a1 / a2 values for our 4 output columns
    float a1x = a[ob + 0], a1y = a[ob + 1], a1z = a[ob + 2], a1w = a[ob + 3];
    float a2x = a[FF + ob + 0], a2y = a[FF + ob + 1], a2z = a[FF + ob + 2], a2w = a[FF + ob + 3];

    #pragma unroll
    for (int ni = 0; ni < 4; ni++) {
        int node = node0 + nb + ni;
        float4 v = make_float4(acc[ni][0], acc[ni][1], acc[ni][2], acc[ni][3]);
        *(float4*)&g_Wh[(size_t)node * FF + ob] = v;

        float p1 = v.x * a1x + v.y * a1y + v.z * a1z + v.w * a1w;
        float p2 = v.x * a2x + v.y * a2y + v.z * a2z + v.w * a2w;
        // reduce across the 16 lanes sharing this node (xor stays within half-warp)
        #pragma unroll
        for (int off = 8; off; off >>= 1) {
            p1 += __shfl_xor_sync(0xffffffffu, p1, off);
            p2 += __shfl_xor_sync(0xffffffffu, p2, off);
        }
        if (ot == 0) {
            g_Wh1[node] = p1;
            g_Wh2[node] = p2;
        }
    }
}

// ---------------------------------------------------------------------------
// Kernel 2: masked LeakyReLU logits -> softmax -> att @ Wh -> ELU.
// Block: 256 threads, 32 query rows per block; grid = 192*16 = 3072.
// smem: att[32][516] (padded) + whs[64][64] + invs[32]
// ---------------------------------------------------------------------------
#define ATT_STRIDE 516
#define SMEM_FLOATS (32 * ATT_STRIDE + FF * FF + 32)
#define SMEM_BYTES (SMEM_FLOATS * 4)

__global__ __launch_bounds__(256) void att_kernel(const float* __restrict__ adj,
                                                  float* __restrict__ out) {
    extern __shared__ float sm[];
    float* att  = sm;                       // 32 * 516
    float* whs  = sm + 32 * ATT_STRIDE;     // 64 * 64
    float* invs = whs + FF * FF;            // 32

    int tid = threadIdx.x;
    int bt = blockIdx.x >> 4;
    int i0 = (blockIdx.x & 15) * 32;
    const float* Wh = g_Wh + (size_t)bt * NN * FF;

    // ---- Phase 1: logits + softmax (unnormalized; 1/s deferred) ----
    int il = tid >> 3;          // 0..31  (query row within tile)
    int jl = tid & 7;           // 8 lanes per row
    int ig = i0 + il;
    float wh1 = g_Wh1[bt * NN + ig];
    const float* adjrow = adj + (size_t)ig * NN;
    const float* wh2p = g_Wh2 + bt * NN;
    float* arow = att + il * ATT_STRIDE;

    float m = NEG_INF_F;
    #pragma unroll 8
    for (int j = jl; j < NN; j += 8) {
        float e = wh1 + wh2p[j];
        e = e > 0.f ? e : ALPHA_F * e;
        e = adjrow[j] > 0.f ? e : NEG_INF_F;
        arow[j] = e;
        m = fmaxf(m, e);
    }
    #pragma unroll
    for (int off = 4; off; off >>= 1)
        m = fmaxf(m, __shfl_xor_sync(0xffffffffu, m, off));

    float s = 0.f;
    #pragma unroll 8
    for (int j = jl; j < NN; j += 8) {
        float p = __expf(arow[j] - m);
        arow[j] = p;
        s += p;
    }
    #pragma unroll
    for (int off = 4; off; off >>= 1)
        s += __shfl_xor_sync(0xffffffffu, s, off);
    if (jl == 0) invs[il] = 1.f / s;
    __syncthreads();

    // ---- Phase 2: out[32 x 64] = att @ Wh, register tiled 2i x 4o ----
    int oq = tid & 15;          // o base = oq*4
    int ir = tid >> 4;          // i pair = {2*ir, 2*ir+1}
    const float* arow0 = att + (2 * ir) * ATT_STRIDE;
    const float* arow1 = arow0 + ATT_STRIDE;

    float4 acc0 = make_float4(0.f, 0.f, 0.f, 0.f);
    float4 acc1 = make_float4(0.f, 0.f, 0.f, 0.f);

    for (int jc = 0; jc < NN; jc += 64) {
        // stage Wh[jc:jc+64][0:64] into smem
        const float4* src = (const float4*)(Wh + (size_t)jc * FF);
        float4* dst = (float4*)whs;
        #pragma unroll
        for (int k = 0; k < 4; k++) dst[tid + k * 256] = src[tid + k * 256];
        __syncthreads();

        #pragma unroll 8
        for (int j = 0; j < 64; j++) {
            float p0 = arow0[jc + j];
            float p1 = arow1[jc + j];
            float4 w = *(const float4*)&whs[j * FF + oq * 4];
            acc0.x += p0 * w.x; acc0.y += p0 * w.y; acc0.z += p0 * w.z; acc0.w += p0 * w.w;
            acc1.x += p1 * w.x; acc1.y += p1 * w.y; acc1.z += p1 * w.z; acc1.w += p1 * w.w;
        }
        __syncthreads();
    }

    // ---- Epilogue: normalize, ELU, store ----
    float is0 = invs[2 * ir], is1 = invs[2 * ir + 1];
    float4 o0, o1;
    o0.x = acc0.x * is0; o0.y = acc0.y * is0; o0.z = acc0.z * is0; o0.w = acc0.w * is0;
    o1.x = acc1.x * is1; o1.y = acc1.y * is1; o1.z = acc1.z * is1; o1.w = acc1.w * is1;

    o0.x = o0.x > 0.f ? o0.x : __expf(o0.x) - 1.f;
    o0.y = o0.y > 0.f ? o0.y : __expf(o0.y) - 1.f;
    o0.z = o0.z > 0.f ? o0.z : __expf(o0.z) - 1.f;
    o0.w = o0.w > 0.f ? o0.w : __expf(o0.w) - 1.f;
    o1.x = o1.x > 0.f ? o1.x : __expf(o1.x) - 1.f;
    o1.y = o1.y > 0.f ? o1.y : __expf(o1.y) - 1.f;
    o1.z = o1.z > 0.f ? o1.z : __expf(o1.z) - 1.f;
    o1.w = o1.w > 0.f ? o1.w : __expf(o1.w) - 1.f;

    size_t row0 = (size_t)(bt * NN + i0 + 2 * ir) * FF + oq * 4;
    *(float4*)&out[row0] = o0;
    *(float4*)&out[row0 + FF] = o1;
}

// ---------------------------------------------------------------------------
extern "C" void kernel_launch(void* const* d_in, const int* in_sizes, int n_in,
                              void* d_out, int out_size) {
    const float* h   = (const float*)d_in[0];   // (16,12,512,64)
    const float* adj = (const float*)d_in[1];   // (512,512)
    const float* W   = (const float*)d_in[2];   // (64,64)
    const float* a   = (const float*)d_in[3];   // (128,1)
    float* out = (float*)d_out;

    cudaFuncSetAttribute(att_kernel, cudaFuncAttributeMaxDynamicSharedMemorySize,
                         SMEM_BYTES);

    wh_kernel<<<(BT * NN) / 32, 128>>>(h, W, a);
    att_kernel<<<BT * 16, 256, SMEM_BYTES>>>(adj, out);
}

// round 4
// speedup vs baseline: 2.4073x; 2.4073x over previous
#include <cuda_runtime.h>
#include <cuda_bf16.h>
#include <cstdint>

#define BT 192
#define NN 512
#define FF 64
#define ALPHA_F 0.2f

// ---------------- device scratch ----------------
__device__ __nv_bfloat16 g_WhT_hi[(size_t)BT * FF * NN];   // [bt*64+o][node]
__device__ __nv_bfloat16 g_WhT_lo[(size_t)BT * FF * NN];
__device__ float g_Wh1[BT * NN];
__device__ float g_Wh2[BT * NN];
__device__ uint32_t g_adjb[NN * 16];                       // adj bitmask

// ---------------- helpers ----------------
__device__ __forceinline__ uint32_t smem_u32(const void* p) {
    uint32_t a;
    asm("{ .reg .u64 t; cvta.to.shared.u64 t, %1; cvt.u32.u64 %0, t; }" : "=r"(a) : "l"(p));
    return a;
}

__device__ __forceinline__ void mma16816(float* c, uint32_t a0, uint32_t a1, uint32_t a2,
                                         uint32_t a3, uint32_t b0, uint32_t b1) {
    asm volatile(
        "mma.sync.aligned.m16n8k16.row.col.f32.bf16.bf16.f32 "
        "{%0,%1,%2,%3}, {%4,%5,%6,%7}, {%8,%9}, {%0,%1,%2,%3};"
        : "+f"(c[0]), "+f"(c[1]), "+f"(c[2]), "+f"(c[3])
        : "r"(a0), "r"(a1), "r"(a2), "r"(a3), "r"(b0), "r"(b1));
}

__device__ __forceinline__ void ldsm4(uint32_t addr, uint32_t& r0, uint32_t& r1,
                                      uint32_t& r2, uint32_t& r3) {
    asm volatile("ldmatrix.sync.aligned.m8n8.x4.shared.b16 {%0,%1,%2,%3}, [%4];"
                 : "=r"(r0), "=r"(r1), "=r"(r2), "=r"(r3) : "r"(addr));
}

__device__ __forceinline__ uint32_t f2bf2(float lo_e, float hi_e) {
    // returns bf16x2 with lo_e in low half
    uint32_t r;
    asm("cvt.rn.bf16x2.f32 %0, %1, %2;" : "=r"(r) : "f"(hi_e), "f"(lo_e));
    return r;
}

// P generation: 4 values (k pairs low8 and +8) for one row, packed split-bf16.
__device__ __forceinline__ void pgen(float wh1v, float2 wa, float2 wb, uint32_t bits, int bb,
                                     int q, uint32_t& hiA, uint32_t& loA, uint32_t& hiB,
                                     uint32_t& loB, float& ssum) {
    float e0 = wh1v + wa.x; e0 = fmaxf(e0, ALPHA_F * e0);
    float e1 = wh1v + wa.y; e1 = fmaxf(e1, ALPHA_F * e1);
    float e2 = wh1v + wb.x; e2 = fmaxf(e2, ALPHA_F * e2);
    float e3 = wh1v + wb.y; e3 = fmaxf(e3, ALPHA_F * e3);
    unsigned b0 = (bits >> (bb + 2 * q)) & 1u;
    unsigned b1 = (bits >> (bb + 2 * q + 1)) & 1u;
    unsigned b2 = (bits >> (bb + 2 * q + 8)) & 1u;
    unsigned b3 = (bits >> (bb + 2 * q + 9)) & 1u;
    float p0 = b0 ? __expf(e0) : 0.f;
    float p1 = b1 ? __expf(e1) : 0.f;
    float p2 = b2 ? __expf(e2) : 0.f;
    float p3 = b3 ? __expf(e3) : 0.f;
    ssum += (p0 + p1) + (p2 + p3);
    uint32_t u0 = __float_as_uint(p0), u1 = __float_as_uint(p1);
    uint32_t u2 = __float_as_uint(p2), u3 = __float_as_uint(p3);
    hiA = __byte_perm(u0, u1, 0x7632);           // {hi(p0), hi(p1)} bf16x2 (trunc)
    hiB = __byte_perm(u2, u3, 0x7632);
    float l0 = p0 - __uint_as_float(u0 & 0xFFFF0000u);
    float l1 = p1 - __uint_as_float(u1 & 0xFFFF0000u);
    float l2 = p2 - __uint_as_float(u2 & 0xFFFF0000u);
    float l3 = p3 - __uint_as_float(u3 & 0xFFFF0000u);
    loA = f2bf2(l0, l1);
    loB = f2bf2(l2, l3);
}

// ---------------------------------------------------------------------------
// Kernel 0: adj -> bitmask. One warp per 32-bit word.
// ---------------------------------------------------------------------------
__global__ __launch_bounds__(256) void adjbits_kernel(const float* __restrict__ adj) {
    int gw = blockIdx.x * 8 + (threadIdx.x >> 5);
    int lane = threadIdx.x & 31;
    int row = gw >> 4, wc = gw & 15;
    float v = adj[row * NN + wc * 32 + lane];
    unsigned m = __ballot_sync(0xffffffffu, v > 0.f);
    if (lane == 0) g_adjb[gw] = m;
}

// ---------------------------------------------------------------------------
// Kernel 1: Wh = h @ W -> transposed split-bf16 WhT (via smem transpose),
//           plus Wh1/Wh2 projections.
// ---------------------------------------------------------------------------
__global__ __launch_bounds__(128) void wh_kernel(const float* __restrict__ h,
                                                 const float* __restrict__ W,
                                                 const float* __restrict__ a) {
    __shared__ float Ws[FF * FF];
    __shared__ float hs[32][68];
    __shared__ __align__(16) __nv_bfloat16 tr_hi[64 * 40];  // stride 40
    __shared__ __align__(16) __nv_bfloat16 tr_lo[64 * 40];

    int tid = threadIdx.x;
    int node0 = blockIdx.x * 32;
    int bt = blockIdx.x >> 4;
    int nloc = (blockIdx.x & 15) * 32;

    const float4* W4 = (const float4*)W;
    float4* Ws4 = (float4*)Ws;
    #pragma unroll
    for (int k = tid; k < FF * FF / 4; k += 128) Ws4[k] = W4[k];

    #pragma unroll
    for (int k = tid; k < 32 * FF / 4; k += 128) {
        int n = k >> 4, c = k & 15;
        float4 v = ((const float4*)(h + (size_t)(node0 + n) * FF))[c];
        hs[n][c * 4 + 0] = v.x; hs[n][c * 4 + 1] = v.y;
        hs[n][c * 4 + 2] = v.z; hs[n][c * 4 + 3] = v.w;
    }
    __syncthreads();

    int ot = tid & 15, nt = tid >> 4;
    int ob = ot * 4, nb = nt * 4;

    float acc[4][4];
    #pragma unroll
    for (int i = 0; i < 4; i++)
        #pragma unroll
        for (int j = 0; j < 4; j++) acc[i][j] = 0.f;

    #pragma unroll 8
    for (int f = 0; f < FF; f++) {
        float4 w = *(const float4*)&Ws[f * FF + ob];
        float h0 = hs[nb + 0][f], h1 = hs[nb + 1][f];
        float h2 = hs[nb + 2][f], h3 = hs[nb + 3][f];
        acc[0][0] += h0 * w.x; acc[0][1] += h0 * w.y; acc[0][2] += h0 * w.z; acc[0][3] += h0 * w.w;
        acc[1][0] += h1 * w.x; acc[1][1] += h1 * w.y; acc[1][2] += h1 * w.z; acc[1][3] += h1 * w.w;
        acc[2][0] += h2 * w.x; acc[2][1] += h2 * w.y; acc[2][2] += h2 * w.z; acc[2][3] += h2 * w.w;
        acc[3][0] += h3 * w.x; acc[3][1] += h3 * w.y; acc[3][2] += h3 * w.z; acc[3][3] += h3 * w.w;
    }

    // transpose tile into smem as split-bf16
    #pragma unroll
    for (int oo = 0; oo < 4; oo++) {
        uint32_t u0 = __float_as_uint(acc[0][oo]), u1 = __float_as_uint(acc[1][oo]);
        uint32_t u2 = __float_as_uint(acc[2][oo]), u3 = __float_as_uint(acc[3][oo]);
        uint2 hi;
        hi.x = __byte_perm(u0, u1, 0x7632);
        hi.y = __byte_perm(u2, u3, 0x7632);
        float l0 = acc[0][oo] - __uint_as_float(u0 & 0xFFFF0000u);
        float l1 = acc[1][oo] - __uint_as_float(u1 & 0xFFFF0000u);
        float l2 = acc[2][oo] - __uint_as_float(u2 & 0xFFFF0000u);
        float l3 = acc[3][oo] - __uint_as_float(u3 & 0xFFFF0000u);
        uint2 lo;
        lo.x = f2bf2(l0, l1);
        lo.y = f2bf2(l2, l3);
        *(uint2*)&tr_hi[(ob + oo) * 40 + nb] = hi;
        *(uint2*)&tr_lo[(ob + oo) * 40 + nb] = lo;
    }

    // Wh1/Wh2 projections
    float a1x = a[ob + 0], a1y = a[ob + 1], a1z = a[ob + 2], a1w = a[ob + 3];
    float a2x = a[FF + ob + 0], a2y = a[FF + ob + 1], a2z = a[FF + ob + 2], a2w = a[FF + ob + 3];
    #pragma unroll
    for (int ni = 0; ni < 4; ni++) {
        float p1 = acc[ni][0] * a1x + acc[ni][1] * a1y + acc[ni][2] * a1z + acc[ni][3] * a1w;
        float p2 = acc[ni][0] * a2x + acc[ni][1] * a2y + acc[ni][2] * a2z + acc[ni][3] * a2w;
        #pragma unroll
        for (int off = 8; off; off >>= 1) {
            p1 += __shfl_xor_sync(0xffffffffu, p1, off);
            p2 += __shfl_xor_sync(0xffffffffu, p2, off);
        }
        if (ot == 0) {
            g_Wh1[node0 + nb + ni] = p1;
            g_Wh2[node0 + nb + ni] = p2;
        }
    }
    __syncthreads();

    // coalesced transposed store: thread -> (o = tid/2, 16-node half)
    int o = tid >> 1, hh = tid & 1;
    const uint4* sh = (const uint4*)(tr_hi + o * 40 + hh * 16);
    const uint4* sl = (const uint4*)(tr_lo + o * 40 + hh * 16);
    size_t dst = ((size_t)(bt * FF + o)) * NN + nloc + hh * 16;
    ((uint4*)(g_WhT_hi + dst))[0] = sh[0];
    ((uint4*)(g_WhT_hi + dst))[1] = sh[1];
    ((uint4*)(g_WhT_lo + dst))[0] = sl[0];
    ((uint4*)(g_WhT_lo + dst))[1] = sl[1];
}

// ---------------------------------------------------------------------------
// Kernel 2: fused mask/softmax/att@Wh/ELU with mma.sync (bf16 split-3).
// Block = 256 thr (8 warps x 32 rows) = 256 rows; grid = BT*2.
// ---------------------------------------------------------------------------
#define SM_WHS_HI 0
#define SM_WHS_LO 8192
#define SM_ADJB 16384
#define SM_WH2 32768
#define SMEM_TOTAL (32768 + 2048)

__global__ __launch_bounds__(256, 2) void att_mma_kernel(float* __restrict__ out) {
    extern __shared__ char smem[];
    uint32_t sbase = smem_u32(smem);
    uint32_t* adjb = (uint32_t*)(smem + SM_ADJB);
    float* wh2s = (float*)(smem + SM_WH2);

    int tid = threadIdx.x;
    int w = tid >> 5, lane = tid & 31;
    int q = lane & 3, tg = lane >> 2;
    int gidx = lane >> 3, li = lane & 7;
    int kh16 = (gidx & 1) << 4;
    int nthalf = gidx >> 1;

    int bt = blockIdx.x >> 1;
    int i0 = (blockIdx.x & 1) << 8;      // 256-row tile

    // stage wh2 + adj bitmask rows
    for (int k = tid; k < NN; k += 256) wh2s[k] = g_Wh2[bt * NN + k];
    {
        const uint4* src = (const uint4*)(g_adjb + i0 * 16);
        uint4* dst = (uint4*)adjb;
        #pragma unroll
        for (int i = 0; i < 4; i++) dst[tid + i * 256] = src[tid + i * 256];
    }

    // wh1 for this thread's 4 rows
    float wh1v[4];
    #pragma unroll
    for (int ri = 0; ri < 4; ri++)
        wh1v[ri] = g_Wh1[bt * NN + i0 + 32 * w + tg + 8 * ri];

    float C[2][8][4];
    #pragma unroll
    for (int mt = 0; mt < 2; mt++)
        #pragma unroll
        for (int nt = 0; nt < 8; nt++)
            #pragma unroll
            for (int r = 0; r < 4; r++) C[mt][nt][r] = 0.f;
    float s_acc[4] = {0.f, 0.f, 0.f, 0.f};

    // per-lane ldmatrix row offsets for the 4 LDSM groups
    uint32_t rowoff[4];
    #pragma unroll
    for (int m = 0; m < 4; m++) {
        int n = (2 * m + nthalf) * 8 + li;
        rowoff[m] = n * 128;
    }
    uint32_t li4 = (uint32_t)(li << 4);

    // per-bt B source, in uint4 units (row pitch = NN halfs = 64 uint4)
    const uint4* srch = (const uint4*)(g_WhT_hi + ((size_t)bt * FF) * NN);
    const uint4* srcl = (const uint4*)(g_WhT_lo + ((size_t)bt * FF) * NN);

    for (int c = 0; c < 8; c++) {
        __syncthreads();
        // stage WhT chunk (64 n-rows x 64 k-halfs) hi/lo, swizzled.
        // chunk col offset within a row = c*64 halfs = c*8 uint4.
        {
            #pragma unroll
            for (int i = 0; i < 2; i++) {
                int idx = tid + i * 256;           // 0..511
                int n = idx >> 3, kq = idx & 7;    // n: 0..63, kq: 0..7 (16B groups)
                uint32_t db = (uint32_t)(n * 128 + ((kq * 16) ^ ((n & 7) << 4)));
                *(uint4*)(smem + SM_WHS_HI + db) = srch[n * 64 + c * 8 + kq];
                *(uint4*)(smem + SM_WHS_LO + db) = srcl[n * 64 + c * 8 + kq];
            }
        }
        __syncthreads();

        // adj words for this chunk (2 words per row)
        uint2 wab[4];
        #pragma unroll
        for (int ri = 0; ri < 4; ri++)
            wab[ri] = *(const uint2*)&adjb[(32 * w + tg + 8 * ri) * 16 + 2 * c];

        #pragma unroll
        for (int s = 0; s < 4; s++) {
            float2 wa = *(const float2*)&wh2s[c * 64 + s * 16 + 2 * q];
            float2 wb = *(const float2*)&wh2s[c * 64 + s * 16 + 2 * q + 8];
            int bb = (s & 1) << 4;

            uint32_t ah[2][4], al[2][4];
            #pragma unroll
            for (int ri = 0; ri < 4; ri++) {
                uint32_t bits = (s < 2) ? wab[ri].x : wab[ri].y;
                uint32_t hiA, loA, hiB, loB;
                pgen(wh1v[ri], wa, wb, bits, bb, q, hiA, loA, hiB, loB, s_acc[ri]);
                int mt = ri >> 1, hf = ri & 1;
                ah[mt][hf] = hiA; ah[mt][hf + 2] = hiB;
                al[mt][hf] = loA; al[mt][hf + 2] = loB;
            }

            uint32_t coloff = (uint32_t)(((s << 5) + kh16) ^ li4);
            #pragma unroll
            for (int m = 0; m < 4; m++) {
                uint32_t bh0, bh1, bh2, bh3, bl0, bl1, bl2, bl3;
                uint32_t ahp = sbase + SM_WHS_HI + rowoff[m] + coloff;
                uint32_t alp = sbase + SM_WHS_LO + rowoff[m] + coloff;
                ldsm4(ahp, bh0, bh1, bh2, bh3);
                ldsm4(alp, bl0, bl1, bl2, bl3);
                #pragma unroll
                for (int mt = 0; mt < 2; mt++) {
                    mma16816(C[mt][2 * m], ah[mt][0], ah[mt][1], ah[mt][2], ah[mt][3], bh0, bh1);
                    mma16816(C[mt][2 * m], al[mt][0], al[mt][1], al[mt][2], al[mt][3], bh0, bh1);
                    mma16816(C[mt][2 * m], ah[mt][0], ah[mt][1], ah[mt][2], ah[mt][3], bl0, bl1);
                    mma16816(C[mt][2 * m + 1], ah[mt][0], ah[mt][1], ah[mt][2], ah[mt][3], bh2, bh3);
                    mma16816(C[mt][2 * m + 1], al[mt][0], al[mt][1], al[mt][2], al[mt][3], bh2, bh3);
                    mma16816(C[mt][2 * m + 1], ah[mt][0], ah[mt][1], ah[mt][2], ah[mt][3], bl2, bl3);
                }
            }
        }
    }

    // row-sum reduce within quads (disjoint k subsets per lane)
    #pragma unroll
    for (int ri = 0; ri < 4; ri++) {
        s_acc[ri] += __shfl_xor_sync(0xffffffffu, s_acc[ri], 1);
        s_acc[ri] += __shfl_xor_sync(0xffffffffu, s_acc[ri], 2);
        s_acc[ri] = 1.f / s_acc[ri];
    }

    // epilogue: normalize, ELU, store
    #pragma unroll
    for (int mt = 0; mt < 2; mt++) {
        int rowl = 32 * w + 16 * mt + tg;
        float* o0 = out + ((size_t)(bt * NN + i0 + rowl)) * FF + 2 * q;
        float* o1 = o0 + 8 * FF;
        float inv0 = s_acc[2 * mt], inv1 = s_acc[2 * mt + 1];
        #pragma unroll
        for (int nt = 0; nt < 8; nt++) {
            float v0 = C[mt][nt][0] * inv0, v1 = C[mt][nt][1] * inv0;
            float v2 = C[mt][nt][2] * inv1, v3 = C[mt][nt][3] * inv1;
            v0 = v0 > 0.f ? v0 : __expf(v0) - 1.f;
            v1 = v1 > 0.f ? v1 : __expf(v1) - 1.f;
            v2 = v2 > 0.f ? v2 : __expf(v2) - 1.f;
            v3 = v3 > 0.f ? v3 : __expf(v3) - 1.f;
            *(float2*)&o0[nt * 8] = make_float2(v0, v1);
            *(float2*)&o1[nt * 8] = make_float2(v2, v3);
        }
    }
}

// ---------------------------------------------------------------------------
extern "C" void kernel_launch(void* const* d_in, const int* in_sizes, int n_in,
                              void* d_out, int out_size) {
    const float* h   = (const float*)d_in[0];
    const float* adj = (const float*)d_in[1];
    const float* W   = (const float*)d_in[2];
    const float* a   = (const float*)d_in[3];
    float* out = (float*)d_out;

    cudaFuncSetAttribute(att_mma_kernel, cudaFuncAttributeMaxDynamicSharedMemorySize,
                         SMEM_TOTAL);

    adjbits_kernel<<<NN * 16 / 8, 256>>>(adj);
    wh_kernel<<<(BT * NN) / 32, 128>>>(h, W, a);
    att_mma_kernel<<<BT * 2, 256, SMEM_TOTAL>>>(out);
}

// round 8
// speedup vs baseline: 2.8335x; 1.1771x over previous
#include <cuda_runtime.h>
#include <cuda_fp16.h>
#include <cstdint>

#define BT 192
#define NN 512
#define FF 64
#define ALPHA_F 0.2f

// ---------------- device scratch ----------------
__device__ __half g_WhT[(size_t)BT * FF * NN];   // [bt*64+o][node], fp16
__device__ float g_Wh1[BT * NN];
__device__ float g_Wh2[BT * NN];
__device__ uint32_t g_adjb[NN * 16];             // adj bitmask

// ---------------- helpers ----------------
__device__ __forceinline__ uint32_t smem_u32(const void* p) {
    uint32_t a;
    asm("{ .reg .u64 t; cvta.to.shared.u64 t, %1; cvt.u32.u64 %0, t; }" : "=r"(a) : "l"(p));
    return a;
}

__device__ __forceinline__ void mma16816(float* c, uint32_t a0, uint32_t a1, uint32_t a2,
                                         uint32_t a3, uint32_t b0, uint32_t b1) {
    asm volatile(
        "mma.sync.aligned.m16n8k16.row.col.f32.f16.f16.f32 "
        "{%0,%1,%2,%3}, {%4,%5,%6,%7}, {%8,%9}, {%0,%1,%2,%3};"
        : "+f"(c[0]), "+f"(c[1]), "+f"(c[2]), "+f"(c[3])
        : "r"(a0), "r"(a1), "r"(a2), "r"(a3), "r"(b0), "r"(b1));
}

__device__ __forceinline__ void ldsm4(uint32_t addr, uint32_t& r0, uint32_t& r1,
                                      uint32_t& r2, uint32_t& r3) {
    asm volatile("ldmatrix.sync.aligned.m8n8.x4.shared.b16 {%0,%1,%2,%3}, [%4];"
                 : "=r"(r0), "=r"(r1), "=r"(r2), "=r"(r3) : "r"(addr));
}

__device__ __forceinline__ uint32_t h2u(__half2 v) {
    return *reinterpret_cast<uint32_t*>(&v);
}

// P generation: 4 values (k pairs low8 and +8) for one row, fp16 split (hi+lo).
__device__ __forceinline__ void pgen(float wh1v, float2 wa, float2 wb, uint32_t bits, int bb,
                                     int q, uint32_t& hiA, uint32_t& loA, uint32_t& hiB,
                                     uint32_t& loB, float& ssum) {
    float e0 = wh1v + wa.x; e0 = fmaxf(e0, ALPHA_F * e0);
    float e1 = wh1v + wa.y; e1 = fmaxf(e1, ALPHA_F * e1);
    float e2 = wh1v + wb.x; e2 = fmaxf(e2, ALPHA_F * e2);
    float e3 = wh1v + wb.y; e3 = fmaxf(e3, ALPHA_F * e3);
    unsigned b0 = (bits >> (bb + 2 * q)) & 1u;
    unsigned b1 = (bits >> (bb + 2 * q + 1)) & 1u;
    unsigned b2 = (bits >> (bb + 2 * q + 8)) & 1u;
    unsigned b3 = (bits >> (bb + 2 * q + 9)) & 1u;
    float p0 = b0 ? __expf(e0) : 0.f;
    float p1 = b1 ? __expf(e1) : 0.f;
    float p2 = b2 ? __expf(e2) : 0.f;
    float p3 = b3 ? __expf(e3) : 0.f;
    ssum += (p0 + p1) + (p2 + p3);

    __half2 h01 = __floats2half2_rn(p0, p1);
    __half2 h23 = __floats2half2_rn(p2, p3);
    hiA = h2u(h01);
    hiB = h2u(h23);
    float l0 = p0 - __low2float(h01);
    float l1 = p1 - __high2float(h01);
    float l2 = p2 - __low2float(h23);
    float l3 = p3 - __high2float(h23);
    loA = h2u(__floats2half2_rn(l0, l1));
    loB = h2u(__floats2half2_rn(l2, l3));
}

// ---------------------------------------------------------------------------
// Kernel 0: adj -> bitmask. Thread handles 4 consecutive floats; nibbles merged
// via shfl. 256 blocks x 256 threads.
// ---------------------------------------------------------------------------
__global__ __launch_bounds__(256) void adjbits_kernel(const float* __restrict__ adj) {
    int t = blockIdx.x * 256 + threadIdx.x;          // float4 index
    float4 v = ((const float4*)adj)[t];
    unsigned nib = (v.x > 0.f ? 1u : 0u) | (v.y > 0.f ? 2u : 0u) |
                   (v.z > 0.f ? 4u : 0u) | (v.w > 0.f ? 8u : 0u);
    unsigned b = nib | (__shfl_down_sync(0xffffffffu, nib, 1) << 4);
    b = b | (__shfl_down_sync(0xffffffffu, b, 2) << 8);
    b = b | (__shfl_down_sync(0xffffffffu, b, 4) << 16);
    if ((threadIdx.x & 7) == 0) g_adjb[t >> 3] = b;
}

// ---------------------------------------------------------------------------
// Kernel 1: Wh = h @ W -> transposed fp16 WhT (via smem transpose),
//           plus Wh1/Wh2 projections.
// ---------------------------------------------------------------------------
__global__ __launch_bounds__(128) void wh_kernel(const float* __restrict__ h,
                                                 const float* __restrict__ W,
                                                 const float* __restrict__ a) {
    __shared__ float Ws[FF * FF];
    __shared__ float hs[32][68];
    __shared__ __align__(16) __half tr[64 * 40];     // stride 40

    int tid = threadIdx.x;
    int node0 = blockIdx.x * 32;
    int bt = blockIdx.x >> 4;
    int nloc = (blockIdx.x & 15) * 32;

    const float4* W4 = (const float4*)W;
    float4* Ws4 = (float4*)Ws;
    #pragma unroll
    for (int k = tid; k < FF * FF / 4; k += 128) Ws4[k] = W4[k];

    #pragma unroll
    for (int k = tid; k < 32 * FF / 4; k += 128) {
        int n = k >> 4, c = k & 15;
        float4 v = ((const float4*)(h + (size_t)(node0 + n) * FF))[c];
        hs[n][c * 4 + 0] = v.x; hs[n][c * 4 + 1] = v.y;
        hs[n][c * 4 + 2] = v.z; hs[n][c * 4 + 3] = v.w;
    }
    __syncthreads();

    int ot = tid & 15, nt = tid >> 4;
    int ob = ot * 4, nb = nt * 4;

    float acc[4][4];
    #pragma unroll
    for (int i = 0; i < 4; i++)
        #pragma unroll
        for (int j = 0; j < 4; j++) acc[i][j] = 0.f;

    #pragma unroll 8
    for (int f = 0; f < FF; f++) {
        float4 w = *(const float4*)&Ws[f * FF + ob];
        float h0 = hs[nb + 0][f], h1 = hs[nb + 1][f];
        float h2 = hs[nb + 2][f], h3 = hs[nb + 3][f];
        acc[0][0] += h0 * w.x; acc[0][1] += h0 * w.y; acc[0][2] += h0 * w.z; acc[0][3] += h0 * w.w;
        acc[1][0] += h1 * w.x; acc[1][1] += h1 * w.y; acc[1][2] += h1 * w.z; acc[1][3] += h1 * w.w;
        acc[2][0] += h2 * w.x; acc[2][1] += h2 * w.y; acc[2][2] += h2 * w.z; acc[2][3] += h2 * w.w;
        acc[3][0] += h3 * w.x; acc[3][1] += h3 * w.y; acc[3][2] += h3 * w.z; acc[3][3] += h3 * w.w;
    }

    // transpose tile into smem as fp16
    #pragma unroll
    for (int oo = 0; oo < 4; oo++) {
        uint2 hv;
        hv.x = h2u(__floats2half2_rn(acc[0][oo], acc[1][oo]));
        hv.y = h2u(__floats2half2_rn(acc[2][oo], acc[3][oo]));
        *(uint2*)&tr[(ob + oo) * 40 + nb] = hv;
    }

    // Wh1/Wh2 projections
    float a1x = a[ob + 0], a1y = a[ob + 1], a1z = a[ob + 2], a1w = a[ob + 3];
    float a2x = a[FF + ob + 0], a2y = a[FF + ob + 1], a2z = a[FF + ob + 2], a2w = a[FF + ob + 3];
    #pragma unroll
    for (int ni = 0; ni < 4; ni++) {
        float p1 = acc[ni][0] * a1x + acc[ni][1] * a1y + acc[ni][2] * a1z + acc[ni][3] * a1w;
        float p2 = acc[ni][0] * a2x + acc[ni][1] * a2y + acc[ni][2] * a2z + acc[ni][3] * a2w;
        #pragma unroll
        for (int off = 8; off; off >>= 1) {
            p1 += __shfl_xor_sync(0xffffffffu, p1, off);
            p2 += __shfl_xor_sync(0xffffffffu, p2, off);
        }
        if (ot == 0) {
            g_Wh1[node0 + nb + ni] = p1;
            g_Wh2[node0 + nb + ni] = p2;
        }
    }
    __syncthreads();

    // coalesced transposed store: thread -> (o = tid/2, 16-node half)
    int o = tid >> 1, hh = tid & 1;
    const uint4* sh = (const uint4*)(tr + o * 40 + hh * 16);
    size_t dst = ((size_t)(bt * FF + o)) * NN + nloc + hh * 16;
    ((uint4*)(g_WhT + dst))[0] = sh[0];
    ((uint4*)(g_WhT + dst))[1] = sh[1];
}

// ---------------------------------------------------------------------------
// Kernel 2: fused mask/softmax/att@Wh/ELU, fp16 mma.sync (A split, B single).
// Block = 256 thr (8 warps x 32 rows) = 256 rows; grid = BT*2.
// smem: B plane 8KB @0, adj bits 16KB @8192, wh2 2KB @24576.
// ---------------------------------------------------------------------------
#define SM_WHS 0
#define SM_ADJB 8192
#define SM_WH2 24576
#define SMEM_TOTAL (24576 + 2048)

__global__ __launch_bounds__(256, 2) void att_mma_kernel(float* __restrict__ out) {
    extern __shared__ char smem[];
    uint32_t sbase = smem_u32(smem);
    uint32_t* adjb = (uint32_t*)(smem + SM_ADJB);
    float* wh2s = (float*)(smem + SM_WH2);

    int tid = threadIdx.x;
    int w = tid >> 5, lane = tid & 31;
    int q = lane & 3, tg = lane >> 2;
    int gidx = lane >> 3, li = lane & 7;
    int kh16 = (gidx & 1) << 4;
    int nthalf = gidx >> 1;

    int bt = blockIdx.x >> 1;
    int i0 = (blockIdx.x & 1) << 8;      // 256-row tile

    // stage wh2 + adj bitmask rows (256 rows x 16 words = 16KB)
    for (int k = tid; k < NN; k += 256) wh2s[k] = g_Wh2[bt * NN + k];
    {
        const uint4* src = (const uint4*)(g_adjb + i0 * 16);
        uint4* dst = (uint4*)adjb;
        #pragma unroll
        for (int i = 0; i < 4; i++) dst[tid + i * 256] = src[tid + i * 256];
    }

    // wh1 for this thread's 4 rows
    float wh1v[4];
    #pragma unroll
    for (int ri = 0; ri < 4; ri++)
        wh1v[ri] = g_Wh1[bt * NN + i0 + 32 * w + tg + 8 * ri];

    float C[2][8][4];
    #pragma unroll
    for (int mt = 0; mt < 2; mt++)
        #pragma unroll
        for (int nt = 0; nt < 8; nt++)
            #pragma unroll
            for (int r = 0; r < 4; r++) C[mt][nt][r] = 0.f;
    float s_acc[4] = {0.f, 0.f, 0.f, 0.f};

    // per-lane ldmatrix row offsets for the 4 LDSM groups
    uint32_t rowoff[4];
    #pragma unroll
    for (int m = 0; m < 4; m++) {
        int n = (2 * m + nthalf) * 8 + li;
        rowoff[m] = n * 128;
    }
    uint32_t li4 = (uint32_t)(li << 4);

    // B source (fp16 plane), row pitch = NN halfs = 64 uint4
    const uint4* src = (const uint4*)(g_WhT + ((size_t)bt * FF) * NN);
    int n0 = tid >> 3, k0 = tid & 7;
    int n1 = (tid + 256) >> 3;
    uint32_t db0 = (uint32_t)(n0 * 128 + ((k0 * 16) ^ ((n0 & 7) << 4)));
    uint32_t db1 = (uint32_t)(n1 * 128 + ((k0 * 16) ^ ((n1 & 7) << 4)));
    uint4 pre0 = src[n0 * 64 + k0];
    uint4 pre1 = src[n1 * 64 + k0];

    for (int c = 0; c < 8; c++) {
        __syncthreads();
        *(uint4*)(smem + SM_WHS + db0) = pre0;
        *(uint4*)(smem + SM_WHS + db1) = pre1;
        __syncthreads();
        if (c < 7) {                      // prefetch next chunk; overlaps compute
            pre0 = src[n0 * 64 + (c + 1) * 8 + k0];
            pre1 = src[n1 * 64 + (c + 1) * 8 + k0];
        }

        // adj words for this chunk (2 words per row)
        uint2 wab[4];
        #pragma unroll
        for (int ri = 0; ri < 4; ri++)
            wab[ri] = *(const uint2*)&adjb[(32 * w + tg + 8 * ri) * 16 + 2 * c];

        #pragma unroll
        for (int s = 0; s < 4; s++) {
            float2 wa = *(const float2*)&wh2s[c * 64 + s * 16 + 2 * q];
            float2 wb = *(const float2*)&wh2s[c * 64 + s * 16 + 2 * q + 8];
            int bb = (s & 1) << 4;

            uint32_t ah[2][4], al[2][4];
            #pragma unroll
            for (int ri = 0; ri < 4; ri++) {
                uint32_t bits = (s < 2) ? wab[ri].x : wab[ri].y;
                uint32_t hiA, loA, hiB, loB;
                pgen(wh1v[ri], wa, wb, bits, bb, q, hiA, loA, hiB, loB, s_acc[ri]);
                int mt = ri >> 1, hf = ri & 1;
                ah[mt][hf] = hiA; ah[mt][hf + 2] = hiB;
                al[mt][hf] = loA; al[mt][hf + 2] = loB;
            }

            uint32_t coloff = (uint32_t)(((s << 5) + kh16) ^ li4);
            #pragma unroll
            for (int m = 0; m < 4; m++) {
                uint32_t bh0, bh1, bh2, bh3;
                ldsm4(sbase + SM_WHS + rowoff[m] + coloff, bh0, bh1, bh2, bh3);
                #pragma unroll
                for (int mt = 0; mt < 2; mt++) {
                    mma16816(C[mt][2 * m], ah[mt][0], ah[mt][1], ah[mt][2], ah[mt][3], bh0, bh1);
                    mma16816(C[mt][2 * m], al[mt][0], al[mt][1], al[mt][2], al[mt][3], bh0, bh1);
                    mma16816(C[mt][2 * m + 1], ah[mt][0], ah[mt][1], ah[mt][2], ah[mt][3], bh2, bh3);
                    mma16816(C[mt][2 * m + 1], al[mt][0], al[mt][1], al[mt][2], al[mt][3], bh2, bh3);
                }
            }
        }
    }

    // row-sum reduce within quads (disjoint k subsets per lane)
    #pragma unroll
    for (int ri = 0; ri < 4; ri++) {
        s_acc[ri] += __shfl_xor_sync(0xffffffffu, s_acc[ri], 1);
        s_acc[ri] += __shfl_xor_sync(0xffffffffu, s_acc[ri], 2);
        s_acc[ri] = 1.f / s_acc[ri];
    }

    // epilogue: normalize, ELU, store
    #pragma unroll
    for (int mt = 0; mt < 2; mt++) {
        int rowl = 32 * w + 16 * mt + tg;
        float* o0 = out + ((size_t)(bt * NN + i0 + rowl)) * FF + 2 * q;
        float* o1 = o0 + 8 * FF;
        float inv0 = s_acc[2 * mt], inv1 = s_acc[2 * mt + 1];
        #pragma unroll
        for (int nt = 0; nt < 8; nt++) {
            float v0 = C[mt][nt][0] * inv0, v1 = C[mt][nt][1] * inv0;
            float v2 = C[mt][nt][2] * inv1, v3 = C[mt][nt][3] * inv1;
            v0 = v0 > 0.f ? v0 : __expf(v0) - 1.f;
            v1 = v1 > 0.f ? v1 : __expf(v1) - 1.f;
            v2 = v2 > 0.f ? v2 : __expf(v2) - 1.f;
            v3 = v3 > 0.f ? v3 : __expf(v3) - 1.f;
            *(float2*)&o0[nt * 8] = make_float2(v0, v1);
            *(float2*)&o1[nt * 8] = make_float2(v2, v3);
        }
    }
}

// ---------------------------------------------------------------------------
extern "C" void kernel_launch(void* const* d_in, const int* in_sizes, int n_in,
                              void* d_out, int out_size) {
    const float* h   = (const float*)d_in[0];
    const float* adj = (const float*)d_in[1];
    const float* W   = (const float*)d_in[2];
    const float* a   = (const float*)d_in[3];
    float* out = (float*)d_out;

    cudaFuncSetAttribute(att_mma_kernel, cudaFuncAttributeMaxDynamicSharedMemorySize,
                         SMEM_TOTAL);

    adjbits_kernel<<<NN * NN / 4 / 256, 256>>>(adj);
    wh_kernel<<<(BT * NN) / 32, 128>>>(h, W, a);
    att_mma_kernel<<<BT * 2, 256, SMEM_TOTAL>>>(out);
}

// round 11
// speedup vs baseline: 4.5876x; 1.6190x over previous
#include <cuda_runtime.h>
#include <cuda_fp16.h>
#include <cstdint>

#define BT 192
#define NN 512
#define FF 64
#define ALPHA_F 0.2f

// ---------------- device scratch ----------------
__device__ __half g_WhT[(size_t)BT * FF * NN];   // [bt*64+o][node], fp16
__device__ float g_Wh1[BT * NN];
__device__ float g_Wh2[BT * NN];
__device__ uint32_t g_adjb[NN * 16];             // adj bitmask

// ---------------- helpers ----------------
__device__ __forceinline__ uint32_t smem_u32(const void* p) {
    uint32_t a;
    asm("{ .reg .u64 t; cvta.to.shared.u64 t, %1; cvt.u32.u64 %0, t; }" : "=r"(a) : "l"(p));
    return a;
}

__device__ __forceinline__ void mma16816(float* c, uint32_t a0, uint32_t a1, uint32_t a2,
                                         uint32_t a3, uint32_t b0, uint32_t b1) {
    asm volatile(
        "mma.sync.aligned.m16n8k16.row.col.f32.f16.f16.f32 "
        "{%0,%1,%2,%3}, {%4,%5,%6,%7}, {%8,%9}, {%0,%1,%2,%3};"
        : "+f"(c[0]), "+f"(c[1]), "+f"(c[2]), "+f"(c[3])
        : "r"(a0), "r"(a1), "r"(a2), "r"(a3), "r"(b0), "r"(b1));
}

__device__ __forceinline__ void ldsm4(uint32_t addr, uint32_t& r0, uint32_t& r1,
                                      uint32_t& r2, uint32_t& r3) {
    asm volatile("ldmatrix.sync.aligned.m8n8.x4.shared.b16 {%0,%1,%2,%3}, [%4];"
                 : "=r"(r0), "=r"(r1), "=r"(r2), "=r"(r3) : "r"(addr));
}

__device__ __forceinline__ uint32_t f2h2(float lo, float hi) {
    // pack two floats into fp16x2 (lo in low half)
    __half2 v = __floats2half2_rn(lo, hi);
    return *reinterpret_cast<uint32_t*>(&v);
}

// P generation via exp tables: 4 values for one row; single fp16 plane.
// ca/cb = (e2p(k0), e2n(k0), e2p(k1), e2n(k1)) for the two k-pairs.
__device__ __forceinline__ void pgen(float nw1, float E1p, float E1n,
                                     float2 wa, float2 wb, float4 ca, float4 cb,
                                     uint32_t bits, int bb, int q,
                                     uint32_t& hiA, uint32_t& hiB, float& ssum) {
    bool c0 = wa.x > nw1;
    bool c1 = wa.y > nw1;
    bool c2 = wb.x > nw1;
    bool c3 = wb.y > nw1;
    float v0 = (c0 ? ca.x : ca.y) * (c0 ? E1p : E1n);
    float v1 = (c1 ? ca.z : ca.w) * (c1 ? E1p : E1n);
    float v2 = (c2 ? cb.x : cb.y) * (c2 ? E1p : E1n);
    float v3 = (c3 ? cb.z : cb.w) * (c3 ? E1p : E1n);
    if (!((bits >> (bb + 2 * q)) & 1u)) v0 = 0.f;
    if (!((bits >> (bb + 2 * q + 1)) & 1u)) v1 = 0.f;
    if (!((bits >> (bb + 2 * q + 8)) & 1u)) v2 = 0.f;
    if (!((bits >> (bb + 2 * q + 9)) & 1u)) v3 = 0.f;
    ssum += (v0 + v1) + (v2 + v3);
    hiA = f2h2(v0, v1);
    hiB = f2h2(v2, v3);
}

// ---------------------------------------------------------------------------
// Kernel 1: blocks [0,3072): Wh = h @ W -> fp16 WhT + Wh1/Wh2.
//           blocks [3072,3584): adj -> bitmask (overlapped).
// ---------------------------------------------------------------------------
__global__ __launch_bounds__(128) void wh_adj_kernel(const float* __restrict__ h,
                                                     const float* __restrict__ W,
                                                     const float* __restrict__ a,
                                                     const float* __restrict__ adj) {
    if (blockIdx.x >= 3072) {
        int t = (blockIdx.x - 3072) * 128 + threadIdx.x;    // float4 index
        float4 v = ((const float4*)adj)[t];
        unsigned nib = (v.x > 0.f ? 1u : 0u) | (v.y > 0.f ? 2u : 0u) |
                       (v.z > 0.f ? 4u : 0u) | (v.w > 0.f ? 8u : 0u);
        unsigned b = nib | (__shfl_down_sync(0xffffffffu, nib, 1) << 4);
        b = b | (__shfl_down_sync(0xffffffffu, b, 2) << 8);
        b = b | (__shfl_down_sync(0xffffffffu, b, 4) << 16);
        if ((threadIdx.x & 7) == 0) g_adjb[t >> 3] = b;
        return;
    }

    __shared__ float Ws[FF * FF];
    __shared__ float hs[32][68];
    __shared__ __align__(16) __half tr[64 * 40];     // stride 40

    int tid = threadIdx.x;
    int node0 = blockIdx.x * 32;
    int bt = blockIdx.x >> 4;
    int nloc = (blockIdx.x & 15) * 32;

    const float4* W4 = (const float4*)W;
    float4* Ws4 = (float4*)Ws;
    #pragma unroll
    for (int k = tid; k < FF * FF / 4; k += 128) Ws4[k] = W4[k];

    #pragma unroll
    for (int k = tid; k < 32 * FF / 4; k += 128) {
        int n = k >> 4, c = k & 15;
        float4 v = ((const float4*)(h + (size_t)(node0 + n) * FF))[c];
        hs[n][c * 4 + 0] = v.x; hs[n][c * 4 + 1] = v.y;
        hs[n][c * 4 + 2] = v.z; hs[n][c * 4 + 3] = v.w;
    }
    __syncthreads();

    int ot = tid & 15, nt = tid >> 4;
    int ob = ot * 4, nb = nt * 4;

    float acc[4][4];
    #pragma unroll
    for (int i = 0; i < 4; i++)
        #pragma unroll
        for (int j = 0; j < 4; j++) acc[i][j] = 0.f;

    #pragma unroll 8
    for (int f = 0; f < FF; f++) {
        float4 w = *(const float4*)&Ws[f * FF + ob];
        float h0 = hs[nb + 0][f], h1 = hs[nb + 1][f];
        float h2 = hs[nb + 2][f], h3 = hs[nb + 3][f];
        acc[0][0] += h0 * w.x; acc[0][1] += h0 * w.y; acc[0][2] += h0 * w.z; acc[0][3] += h0 * w.w;
        acc[1][0] += h1 * w.x; acc[1][1] += h1 * w.y; acc[1][2] += h1 * w.z; acc[1][3] += h1 * w.w;
        acc[2][0] += h2 * w.x; acc[2][1] += h2 * w.y; acc[2][2] += h2 * w.z; acc[2][3] += h2 * w.w;
        acc[3][0] += h3 * w.x; acc[3][1] += h3 * w.y; acc[3][2] += h3 * w.z; acc[3][3] += h3 * w.w;
    }

    // transpose tile into smem as fp16
    #pragma unroll
    for (int oo = 0; oo < 4; oo++) {
        uint2 hv;
        hv.x = f2h2(acc[0][oo], acc[1][oo]);
        hv.y = f2h2(acc[2][oo], acc[3][oo]);
        *(uint2*)&tr[(ob + oo) * 40 + nb] = hv;
    }

    // Wh1/Wh2 projections
    float a1x = a[ob + 0], a1y = a[ob + 1], a1z = a[ob + 2], a1w = a[ob + 3];
    float a2x = a[FF + ob + 0], a2y = a[FF + ob + 1], a2z = a[FF + ob + 2], a2w = a[FF + ob + 3];
    #pragma unroll
    for (int ni = 0; ni < 4; ni++) {
        float p1 = acc[ni][0] * a1x + acc[ni][1] * a1y + acc[ni][2] * a1z + acc[ni][3] * a1w;
        float p2 = acc[ni][0] * a2x + acc[ni][1] * a2y + acc[ni][2] * a2z + acc[ni][3] * a2w;
        #pragma unroll
        for (int off = 8; off; off >>= 1) {
            p1 += __shfl_xor_sync(0xffffffffu, p1, off);
            p2 += __shfl_xor_sync(0xffffffffu, p2, off);
        }
        if (ot == 0) {
            g_Wh1[node0 + nb + ni] = p1;
            g_Wh2[node0 + nb + ni] = p2;
        }
    }
    __syncthreads();

    // coalesced transposed store: thread -> (o = tid/2, 16-node half)
    int o = tid >> 1, hh = tid & 1;
    const uint4* sh = (const uint4*)(tr + o * 40 + hh * 16);
    size_t dst = ((size_t)(bt * FF + o)) * NN + nloc + hh * 16;
    ((uint4*)(g_WhT + dst))[0] = sh[0];
    ((uint4*)(g_WhT + dst))[1] = sh[1];
}

// ---------------------------------------------------------------------------
// Kernel 2: fused mask/softmax/att@Wh/ELU; fp16 mma, exp tables (no MUFU in
// hot loop). Block = 256 thr (8 warps x 32 rows) = 256 rows; grid = BT*2.
// smem: B plane 8KB @0, adj bits 16KB @8192, wh2 2KB @24576, exp tables 4KB.
// ---------------------------------------------------------------------------
#define SM_WHS 0
#define SM_ADJB 8192
#define SM_WH2 24576
#define SM_CMB 26624
#define SMEM_TOTAL 30720

__global__ __launch_bounds__(256, 2) void att_mma_kernel(float* __restrict__ out) {
    extern __shared__ char smem[];
    uint32_t sbase = smem_u32(smem);
    uint32_t* adjb = (uint32_t*)(smem + SM_ADJB);
    float* wh2s = (float*)(smem + SM_WH2);
    float2* cmb = (float2*)(smem + SM_CMB);      // (exp(wh2), exp(0.2*wh2))

    int tid = threadIdx.x;
    int w = tid >> 5, lane = tid & 31;
    int q = lane & 3, tg = lane >> 2;
    int gidx = lane >> 3, li = lane & 7;
    int kh16 = (gidx & 1) << 4;
    int nthalf = gidx >> 1;

    int bt = blockIdx.x >> 1;
    int i0 = (blockIdx.x & 1) << 8;      // 256-row tile

    // stage wh2 + exp tables + adj bitmask rows
    for (int k = tid; k < NN; k += 256) {
        float w2 = g_Wh2[bt * NN + k];
        wh2s[k] = w2;
        cmb[k] = make_float2(__expf(w2), __expf(ALPHA_F * w2));
    }
    {
        const uint4* src = (const uint4*)(g_adjb + i0 * 16);
        uint4* dst = (uint4*)adjb;
        #pragma unroll
        for (int i = 0; i < 4; i++) dst[tid + i * 256] = src[tid + i * 256];
    }

    // per-row constants for this thread's 4 rows
    float nw1[4], E1p[4], E1n[4];
    #pragma unroll
    for (int ri = 0; ri < 4; ri++) {
        float w1 = g_Wh1[bt * NN + i0 + 32 * w + tg + 8 * ri];
        nw1[ri] = -w1;
        E1p[ri] = __expf(w1);
        E1n[ri] = __expf(ALPHA_F * w1);
    }

    float C[2][8][4];
    #pragma unroll
    for (int mt = 0; mt < 2; mt++)
        #pragma unroll
        for (int nt = 0; nt < 8; nt++)
            #pragma unroll
            for (int r = 0; r < 4; r++) C[mt][nt][r] = 0.f;
    float s_acc[4] = {0.f, 0.f, 0.f, 0.f};

    // per-lane ldmatrix row offsets for the 4 LDSM groups
    uint32_t rowoff[4];
    #pragma unroll
    for (int m = 0; m < 4; m++) {
        int n = (2 * m + nthalf) * 8 + li;
        rowoff[m] = n * 128;
    }
    uint32_t li4 = (uint32_t)(li << 4);

    // B source (fp16 plane), row pitch = NN halfs = 64 uint4
    const uint4* src = (const uint4*)(g_WhT + ((size_t)bt * FF) * NN);
    int n0 = tid >> 3, k0 = tid & 7;
    int n1 = (tid + 256) >> 3;
    uint32_t db0 = (uint32_t)(n0 * 128 + ((k0 * 16) ^ ((n0 & 7) << 4)));
    uint32_t db1 = (uint32_t)(n1 * 128 + ((k0 * 16) ^ ((n1 & 7) << 4)));
    uint4 pre0 = src[n0 * 64 + k0];
    uint4 pre1 = src[n1 * 64 + k0];

    for (int c = 0; c < 8; c++) {
        __syncthreads();
        *(uint4*)(smem + SM_WHS + db0) = pre0;
        *(uint4*)(smem + SM_WHS + db1) = pre1;
        __syncthreads();
        if (c < 7) {                      // prefetch next chunk; overlaps compute
            pre0 = src[n0 * 64 + (c + 1) * 8 + k0];
            pre1 = src[n1 * 64 + (c + 1) * 8 + k0];
        }

        // adj words for this chunk (2 words per row)
        uint2 wab[4];
        #pragma unroll
        for (int ri = 0; ri < 4; ri++)
            wab[ri] = *(const uint2*)&adjb[(32 * w + tg + 8 * ri) * 16 + 2 * c];

        #pragma unroll
        for (int s = 0; s < 4; s++) {
            int kb = c * 64 + s * 16 + 2 * q;
            float2 wa = *(const float2*)&wh2s[kb];
            float2 wb = *(const float2*)&wh2s[kb + 8];
            float4 ca = *(const float4*)&cmb[kb];        // (e2p,e2n) x2
            float4 cb = *(const float4*)&cmb[kb + 8];
            int bb = (s & 1) << 4;

            uint32_t ah[2][4];
            #pragma unroll
            for (int ri = 0; ri < 4; ri++) {
                uint32_t bits = (s < 2) ? wab[ri].x : wab[ri].y;
                uint32_t hiA, hiB;
                pgen(nw1[ri], E1p[ri], E1n[ri], wa, wb, ca, cb, bits, bb, q,
                     hiA, hiB, s_acc[ri]);
                int mt = ri >> 1, hf = ri & 1;
                ah[mt][hf] = hiA; ah[mt][hf + 2] = hiB;
            }

            uint32_t coloff = (uint32_t)(((s << 5) + kh16) ^ li4);
            #pragma unroll
            for (int m = 0; m < 4; m++) {
                uint32_t bh0, bh1, bh2, bh3;
                ldsm4(sbase + SM_WHS + rowoff[m] + coloff, bh0, bh1, bh2, bh3);
                #pragma unroll
                for (int mt = 0; mt < 2; mt++) {
                    mma16816(C[mt][2 * m], ah[mt][0], ah[mt][1], ah[mt][2], ah[mt][3], bh0, bh1);
                    mma16816(C[mt][2 * m + 1], ah[mt][0], ah[mt][1], ah[mt][2], ah[mt][3], bh2, bh3);
                }
            }
        }
    }

    // row-sum reduce within quads (disjoint k subsets per lane)
    #pragma unroll
    for (int ri = 0; ri < 4; ri++) {
        s_acc[ri] += __shfl_xor_sync(0xffffffffu, s_acc[ri], 1);
        s_acc[ri] += __shfl_xor_sync(0xffffffffu, s_acc[ri], 2);
        s_acc[ri] = 1.f / s_acc[ri];
    }

    // epilogue: normalize, ELU, store
    #pragma unroll
    for (int mt = 0; mt < 2; mt++) {
        int rowl = 32 * w + 16 * mt + tg;
        float* o0 = out + ((size_t)(bt * NN + i0 + rowl)) * FF + 2 * q;
        float* o1 = o0 + 8 * FF;
        float inv0 = s_acc[2 * mt], inv1 = s_acc[2 * mt + 1];
        #pragma unroll
        for (int nt = 0; nt < 8; nt++) {
            float v0 = C[mt][nt][0] * inv0, v1 = C[mt][nt][1] * inv0;
            float v2 = C[mt][nt][2] * inv1, v3 = C[mt][nt][3] * inv1;
            v0 = v0 > 0.f ? v0 : __expf(v0) - 1.f;
            v1 = v1 > 0.f ? v1 : __expf(v1) - 1.f;
            v2 = v2 > 0.f ? v2 : __expf(v2) - 1.f;
            v3 = v3 > 0.f ? v3 : __expf(v3) - 1.f;
            *(float2*)&o0[nt * 8] = make_float2(v0, v1);
            *(float2*)&o1[nt * 8] = make_float2(v2, v3);
        }
    }
}

// ---------------------------------------------------------------------------
extern "C" void kernel_launch(void* const* d_in, const int* in_sizes, int n_in,
                              void* d_out, int out_size) {
    const float* h   = (const float*)d_in[0];
    const float* adj = (const float*)d_in[1];
    const float* W   = (const float*)d_in[2];
    const float* a   = (const float*)d_in[3];
    float* out = (float*)d_out;

    cudaFuncSetAttribute(att_mma_kernel, cudaFuncAttributeMaxDynamicSharedMemorySize,
                         SMEM_TOTAL);

    wh_adj_kernel<<<3072 + 512, 128>>>(h, W, a, adj);
    att_mma_kernel<<<BT * 2, 256, SMEM_TOTAL>>>(out);
}

// round 12
// speedup vs baseline: 5.9847x; 1.3045x over previous
#include <cuda_runtime.h>
#include <cuda_fp16.h>
#include <cstdint>

#define BT 192
#define NN 512
#define FF 64
#define ALPHA_F 0.2f

// ---------------- device scratch ----------------
__device__ __half g_Wh[(size_t)BT * NN * FF];    // [bt][node][o], fp16
__device__ float g_Wh1[BT * NN];
__device__ float g_Wh2[BT * NN];
__device__ uint32_t g_adjb[NN * 16];             // adj bitmask

// ---------------- helpers ----------------
__device__ __forceinline__ uint32_t smem_u32(const void* p) {
    uint32_t a;
    asm("{ .reg .u64 t; cvta.to.shared.u64 t, %1; cvt.u32.u64 %0, t; }" : "=r"(a) : "l"(p));
    return a;
}
__device__ __forceinline__ uint32_t h2u(__half2 v) { return *reinterpret_cast<uint32_t*>(&v); }
__device__ __forceinline__ __half2 u2h(uint32_t u) { return *reinterpret_cast<__half2*>(&u); }

__device__ __forceinline__ void mma16816(float* c, uint32_t a0, uint32_t a1, uint32_t a2,
                                         uint32_t a3, uint32_t b0, uint32_t b1) {
    asm volatile(
        "mma.sync.aligned.m16n8k16.row.col.f32.f16.f16.f32 "
        "{%0,%1,%2,%3}, {%4,%5,%6,%7}, {%8,%9}, {%0,%1,%2,%3};"
        : "+f"(c[0]), "+f"(c[1]), "+f"(c[2]), "+f"(c[3])
        : "r"(a0), "r"(a1), "r"(a2), "r"(a3), "r"(b0), "r"(b1));
}
__device__ __forceinline__ void ldsm4(uint32_t addr, uint32_t& r0, uint32_t& r1,
                                      uint32_t& r2, uint32_t& r3) {
    asm volatile("ldmatrix.sync.aligned.m8n8.x4.shared.b16 {%0,%1,%2,%3}, [%4];"
                 : "=r"(r0), "=r"(r1), "=r"(r2), "=r"(r3) : "r"(addr));
}
__device__ __forceinline__ void ldsm4t(uint32_t addr, uint32_t& r0, uint32_t& r1,
                                       uint32_t& r2, uint32_t& r3) {
    asm volatile("ldmatrix.sync.aligned.m8n8.x4.trans.shared.b16 {%0,%1,%2,%3}, [%4];"
                 : "=r"(r0), "=r"(r1), "=r"(r2), "=r"(r3) : "r"(addr));
}
// per-half 0xFFFF mask where a > b (f16x2)
__device__ __forceinline__ uint32_t hgt2_mask(uint32_t a, uint32_t b) {
    uint32_t m;
    asm("set.gt.u32.f16x2 %0, %1, %2;" : "=r"(m) : "r"(a), "r"(b));
    return m;
}

// ---------------------------------------------------------------------------
// Kernel 1: blocks [0,768): Wh = h @ W via split-fp16 mma (3 planes) ->
//           g_Wh [node][o] fp16 + exact fp32 Wh1/Wh2.
//           blocks [768,1280): adj -> bitmask.
// smem: A-hi 16KB @0, A-lo 16KB @16384, W-hi 8KB @32768, W-lo 8KB @40960,
//       a vec 512B @49152.  total 49664 (dynamic).
// ---------------------------------------------------------------------------
#define WH_SMEM 49664
__global__ __launch_bounds__(128) void wh_mma_kernel(const float* __restrict__ h,
                                                     const float* __restrict__ W,
                                                     const float* __restrict__ a,
                                                     const float* __restrict__ adj) {
    if (blockIdx.x >= 768) {
        int t = (blockIdx.x - 768) * 128 + threadIdx.x;     // float4 index
        float4 v = ((const float4*)adj)[t];
        unsigned nib = (v.x > 0.f ? 1u : 0u) | (v.y > 0.f ? 2u : 0u) |
                       (v.z > 0.f ? 4u : 0u) | (v.w > 0.f ? 8u : 0u);
        unsigned b = nib | (__shfl_down_sync(0xffffffffu, nib, 1) << 4);
        b = b | (__shfl_down_sync(0xffffffffu, b, 2) << 8);
        b = b | (__shfl_down_sync(0xffffffffu, b, 4) << 16);
        if ((threadIdx.x & 7) == 0) g_adjb[t >> 3] = b;
        return;
    }

    extern __shared__ char sm[];
    uint32_t sbase = smem_u32(sm);
    float* sa = (float*)(sm + 49152);

    int tid = threadIdx.x;
    int wid = tid >> 5, lane = tid & 31;
    int bt = blockIdx.x >> 2;
    int nwin = (blockIdx.x & 3) * 128;

    // 1) stage W fp32 into sm[0:16384) ; stage a
    {
        float4* d = (float4*)sm;
        const float4* s4 = (const float4*)W;
        #pragma unroll
        for (int i = 0; i < 8; i++) d[tid + i * 128] = s4[tid + i * 128];
        sa[tid] = a[tid];
    }
    __syncthreads();

    // 2) transpose+split W -> Wt[o][f] hi/lo planes (swizzled 128B rows)
    {
        const float* w32 = (const float*)sm;
        int o = tid >> 1, fh = (tid & 1) * 32;
        uint4 hi[4], lo[4];
        #pragma unroll
        for (int g = 0; g < 4; g++) {
            float v[8];
            #pragma unroll
            for (int j = 0; j < 8; j++) v[j] = w32[(fh + g * 8 + j) * 64 + o];
            uint32_t hw[4], lw[4];
            #pragma unroll
            for (int p = 0; p < 4; p++) {
                __half2 hh = __floats2half2_rn(v[2 * p], v[2 * p + 1]);
                hw[p] = h2u(hh);
                lw[p] = h2u(__floats2half2_rn(v[2 * p] - __low2float(hh),
                                              v[2 * p + 1] - __high2float(hh)));
            }
            hi[g] = make_uint4(hw[0], hw[1], hw[2], hw[3]);
            lo[g] = make_uint4(lw[0], lw[1], lw[2], lw[3]);
        }
        __syncthreads();   // all reads of w32 done before overwriting region? (W region reused below only by A planes @0..32768; Wt planes live at 32768+)
        #pragma unroll
        for (int g = 0; g < 4; g++) {
            uint32_t dst = (uint32_t)(o * 128 + ((fh * 2 + g * 16) ^ ((o & 7) << 4)));
            *(uint4*)(sm + 32768 + dst) = hi[g];
            *(uint4*)(sm + 40960 + dst) = lo[g];
        }
    }
    __syncthreads();

    // 3) stage h row -> A hi/lo planes (row = tid)
    {
        int r = tid;
        const float4* hr = (const float4*)(h + ((size_t)(bt * 512 + nwin + r)) * 64);
        #pragma unroll
        for (int g = 0; g < 8; g++) {
            float4 x = hr[2 * g], y = hr[2 * g + 1];
            __half2 h0 = __floats2half2_rn(x.x, x.y), h1 = __floats2half2_rn(x.z, x.w);
            __half2 h2 = __floats2half2_rn(y.x, y.y), h3 = __floats2half2_rn(y.z, y.w);
            uint4 hi = make_uint4(h2u(h0), h2u(h1), h2u(h2), h2u(h3));
            uint4 lo = make_uint4(
                h2u(__floats2half2_rn(x.x - __low2float(h0), x.y - __high2float(h0))),
                h2u(__floats2half2_rn(x.z - __low2float(h1), x.w - __high2float(h1))),
                h2u(__floats2half2_rn(y.x - __low2float(h2), y.y - __high2float(h2))),
                h2u(__floats2half2_rn(y.z - __low2float(h3), y.w - __high2float(h3))));
            uint32_t dst = (uint32_t)(r * 128 + ((g * 16) ^ ((r & 7) << 4)));
            *(uint4*)(sm + dst) = hi;
            *(uint4*)(sm + 16384 + dst) = lo;
        }
    }
    __syncthreads();

    // 4) MMA: per warp 32 rows x 64 cols, k=64; planes hh + hl + lh
    float C[2][8][4];
    #pragma unroll
    for (int mt = 0; mt < 2; mt++)
        #pragma unroll
        for (int nt = 0; nt < 8; nt++)
            #pragma unroll
            for (int r = 0; r < 4; r++) C[mt][nt][r] = 0.f;

    int li = lane & 7, gidx = lane >> 3, nthalf = gidx >> 1, kh16 = (gidx & 1) << 4;
    uint32_t ro_a = (uint32_t)((wid * 32 + (lane & 15)) * 128);
    uint32_t xw_a = (uint32_t)((lane >> 4) * 16);
    uint32_t swz_a = (uint32_t)((lane & 7) << 4);
    uint32_t rowW[4];
    #pragma unroll
    for (int m = 0; m < 4; m++)
        rowW[m] = 32768u + (uint32_t)(((2 * m + nthalf) * 8 + li) * 128);

    #pragma unroll
    for (int s = 0; s < 4; s++) {
        uint32_t ac = (uint32_t)((s * 32 + xw_a) ^ swz_a);
        uint32_t Ah[2][4], Al[2][4];
        ldsm4(sbase + ro_a + ac, Ah[0][0], Ah[0][1], Ah[0][2], Ah[0][3]);
        ldsm4(sbase + ro_a + 2048 + ac, Ah[1][0], Ah[1][1], Ah[1][2], Ah[1][3]);
        ldsm4(sbase + 16384 + ro_a + ac, Al[0][0], Al[0][1], Al[0][2], Al[0][3]);
        ldsm4(sbase + 16384 + ro_a + 2048 + ac, Al[1][0], Al[1][1], Al[1][2], Al[1][3]);
        uint32_t wc = (uint32_t)(((s << 5) + kh16) ^ (li << 4));
        #pragma unroll
        for (int m = 0; m < 4; m++) {
            uint32_t bh0, bh1, bh2, bh3, bl0, bl1, bl2, bl3;
            ldsm4(sbase + rowW[m] + wc, bh0, bh1, bh2, bh3);
            ldsm4(sbase + rowW[m] + 8192 + wc, bl0, bl1, bl2, bl3);
            #pragma unroll
            for (int mt = 0; mt < 2; mt++) {
                mma16816(C[mt][2 * m], Ah[mt][0], Ah[mt][1], Ah[mt][2], Ah[mt][3], bh0, bh1);
                mma16816(C[mt][2 * m], Al[mt][0], Al[mt][1], Al[mt][2], Al[mt][3], bh0, bh1);
                mma16816(C[mt][2 * m], Ah[mt][0], Ah[mt][1], Ah[mt][2], Ah[mt][3], bl0, bl1);
                mma16816(C[mt][2 * m + 1], Ah[mt][0], Ah[mt][1], Ah[mt][2], Ah[mt][3], bh2, bh3);
                mma16816(C[mt][2 * m + 1], Al[mt][0], Al[mt][1], Al[mt][2], Al[mt][3], bh2, bh3);
                mma16816(C[mt][2 * m + 1], Ah[mt][0], Ah[mt][1], Ah[mt][2], Ah[mt][3], bl2, bl3);
            }
        }
    }

    // 5) epilogue: fp16 Wh [node][o] + fp32 Wh1/Wh2
    int tg = lane >> 2, q = lane & 3;
    #pragma unroll
    for (int mt = 0; mt < 2; mt++) {
        int rbase = bt * 512 + nwin + wid * 32 + mt * 16 + tg;
        float p1a = 0.f, p2a = 0.f, p1b = 0.f, p2b = 0.f;
        #pragma unroll
        for (int nt = 0; nt < 8; nt++) {
            float c0 = C[mt][nt][0], c1 = C[mt][nt][1];
            float c2 = C[mt][nt][2], c3 = C[mt][nt][3];
            *(uint32_t*)(g_Wh + (size_t)rbase * 64 + nt * 8 + 2 * q) =
                h2u(__floats2half2_rn(c0, c1));
            *(uint32_t*)(g_Wh + (size_t)(rbase + 8) * 64 + nt * 8 + 2 * q) =
                h2u(__floats2half2_rn(c2, c3));
            float a1l = sa[nt * 8 + 2 * q], a1h = sa[nt * 8 + 2 * q + 1];
            float a2l = sa[64 + nt * 8 + 2 * q], a2h = sa[64 + nt * 8 + 2 * q + 1];
            p1a += c0 * a1l + c1 * a1h;  p2a += c0 * a2l + c1 * a2h;
            p1b += c2 * a1l + c3 * a1h;  p2b += c2 * a2l + c3 * a2h;
        }
        p1a += __shfl_xor_sync(0xffffffffu, p1a, 1); p1a += __shfl_xor_sync(0xffffffffu, p1a, 2);
        p2a += __shfl_xor_sync(0xffffffffu, p2a, 1); p2a += __shfl_xor_sync(0xffffffffu, p2a, 2);
        p1b += __shfl_xor_sync(0xffffffffu, p1b, 1); p1b += __shfl_xor_sync(0xffffffffu, p1b, 2);
        p2b += __shfl_xor_sync(0xffffffffu, p2b, 1); p2b += __shfl_xor_sync(0xffffffffu, p2b, 2);
        if (q == 0) {
            g_Wh1[rbase] = p1a;     g_Wh2[rbase] = p2a;
            g_Wh1[rbase + 8] = p1b; g_Wh2[rbase + 8] = p2b;
        }
    }
}

// ---------------------------------------------------------------------------
// Kernel 2: fused att. Packed half2 pgen (bit-select, exp tables), adj by
// bit-AND, row sums via ones-column MMA, double-buffered B with ldsm.trans.
// smem: B0 8KB @0, B1 8KB @8192, adj 16KB @16384, tbl 2KB @32768, whh 1KB @34816.
// ---------------------------------------------------------------------------
#define SM_B0 0
#define SM_B1 8192
#define SM_ADJ 16384
#define SM_TBL 32768
#define SM_WHH 34816
#define ATT_SMEM 35840

__global__ __launch_bounds__(256, 2) void att_mma_kernel(float* __restrict__ out) {
    extern __shared__ char smem[];
    uint32_t sbase = smem_u32(smem);
    uint2* tbl = (uint2*)(smem + SM_TBL);        // (e2p_h2, e2n_h2) per col pair
    uint32_t* whh = (uint32_t*)(smem + SM_WHH);  // wh2 half2 per col pair
    uint32_t* adjb = (uint32_t*)(smem + SM_ADJ);

    int tid = threadIdx.x;
    int w = tid >> 5, lane = tid & 31;
    int q = lane & 3, tg = lane >> 2;
    int bt = blockIdx.x >> 1;
    int i0 = (blockIdx.x & 1) << 8;

    // stage exp tables + adj bits
    {
        int k2 = tid;                            // 0..255 exactly
        float w2a = g_Wh2[bt * 512 + 2 * k2];
        float w2b = g_Wh2[bt * 512 + 2 * k2 + 1];
        tbl[k2] = make_uint2(h2u(__floats2half2_rn(__expf(w2a), __expf(w2b))),
                             h2u(__floats2half2_rn(__expf(ALPHA_F * w2a), __expf(ALPHA_F * w2b))));
        whh[k2] = h2u(__floats2half2_rn(w2a, w2b));
    }
    {
        const uint4* src = (const uint4*)(g_adjb + i0 * 16);
        uint4* dst = (uint4*)adjb;
        #pragma unroll
        for (int i = 0; i < 4; i++) dst[tid + i * 256] = src[tid + i * 256];
    }

    // per-row constants
    uint32_t unw1[4], uE1p[4], uE1n[4];
    #pragma unroll
    for (int ri = 0; ri < 4; ri++) {
        float w1 = g_Wh1[bt * 512 + i0 + 32 * w + tg + 8 * ri];
        unw1[ri] = h2u(__floats2half2_rn(-w1, -w1));
        float ep = __expf(w1), en = __expf(ALPHA_F * w1);
        uE1p[ri] = h2u(__floats2half2_rn(ep, ep));
        uE1n[ri] = h2u(__floats2half2_rn(en, en));
    }

    float C[2][8][4];
    #pragma unroll
    for (int mt = 0; mt < 2; mt++)
        #pragma unroll
        for (int nt = 0; nt < 8; nt++)
            #pragma unroll
            for (int r = 0; r < 4; r++) C[mt][nt][r] = 0.f;
    float Cs[2][4] = {{0.f, 0.f, 0.f, 0.f}, {0.f, 0.f, 0.f, 0.f}};
    uint32_t bone = (lane < 4) ? 0x3C003C00u : 0u;   // ones column n=0

    // trans-B addressing (k-major smem [node][o])
    uint32_t ro = (uint32_t)((lane & 15) * 128);
    uint32_t cm[4];
    {
        uint32_t xw = (uint32_t)((lane >> 4) * 16);
        uint32_t swz = (uint32_t)((lane & 7) << 4);
        #pragma unroll
        for (int m = 0; m < 4; m++) cm[m] = (m * 32 + xw) ^ swz;
    }

    // staging: chunk = 64 node-rows x 128B
    const uint4* srcW = (const uint4*)(g_Wh + (size_t)bt * 512 * 64);
    int n0 = tid >> 3, g0 = tid & 7;
    int n1 = (tid + 256) >> 3;
    uint32_t db0 = (uint32_t)(n0 * 128 + ((g0 * 16) ^ ((n0 & 7) << 4)));
    uint32_t db1 = (uint32_t)(n1 * 128 + ((g0 * 16) ^ ((n1 & 7) << 4)));
    uint4 pre0 = srcW[tid], pre1 = srcW[tid + 256];
    *(uint4*)(smem + SM_B0 + db0) = pre0;
    *(uint4*)(smem + SM_B0 + db1) = pre1;
    __syncthreads();

    for (int c = 0; c < 8; c++) {
        if (c < 7) {
            pre0 = srcW[(c + 1) * 512 + tid];
            pre1 = srcW[(c + 1) * 512 + tid + 256];
        }
        uint32_t bufb = sbase + ((c & 1) ? SM_B1 : SM_B0);

        uint32_t rx[4], ry[4];
        #pragma unroll
        for (int ri = 0; ri < 4; ri++) {
            uint2 wv = *(const uint2*)&adjb[(32 * w + tg + 8 * ri) * 16 + 2 * c];
            rx[ri] = wv.x >> (2 * q);
            ry[ri] = wv.y >> (2 * q);
        }

        #pragma unroll
        for (int s = 0; s < 4; s++) {
            int idx = c * 32 + s * 8 + q;
            uint2 eA = tbl[idx], eB = tbl[idx + 4];
            uint32_t whA = whh[idx], whB = whh[idx + 4];

            uint32_t ah[2][4];
            #pragma unroll
            for (int ri = 0; ri < 4; ri++) {
                uint32_t u = (s == 0) ? rx[ri] : (s == 1) ? (rx[ri] >> 16)
                           : (s == 2) ? ry[ri] : (ry[ri] >> 16);
                uint32_t mA = hgt2_mask(whA, unw1[ri]);
                uint32_t mB = hgt2_mask(whB, unw1[ri]);
                uint32_t e2A = (eA.x & mA) | (eA.y & ~mA);
                uint32_t E1A = (uE1p[ri] & mA) | (uE1n[ri] & ~mA);
                uint32_t e2B = (eB.x & mB) | (eB.y & ~mB);
                uint32_t E1B = (uE1p[ri] & mB) | (uE1n[ri] & ~mB);
                uint32_t vA = h2u(__hmul2(u2h(e2A), u2h(E1A)));
                uint32_t vB = h2u(__hmul2(u2h(e2B), u2h(E1B)));
                uint32_t amA = ((u & 1u) ? 0xFFFFu : 0u) | ((u & 2u) ? 0xFFFF0000u : 0u);
                uint32_t amB = ((u & 0x100u) ? 0xFFFFu : 0u) | ((u & 0x200u) ? 0xFFFF0000u : 0u);
                vA &= amA;
                vB &= amB;
                ah[ri >> 1][ri & 1] = vA;
                ah[ri >> 1][(ri & 1) + 2] = vB;
            }

            uint32_t rbase = bufb + (uint32_t)(s * 2048) + ro;
            #pragma unroll
            for (int m = 0; m < 4; m++) {
                uint32_t b0, b1, b2, b3;
                ldsm4t(rbase + cm[m], b0, b1, b2, b3);
                #pragma unroll
                for (int mt = 0; mt < 2; mt++) {
                    mma16816(C[mt][2 * m], ah[mt][0], ah[mt][1], ah[mt][2], ah[mt][3], b0, b1);
                    mma16816(C[mt][2 * m + 1], ah[mt][0], ah[mt][1], ah[mt][2], ah[mt][3], b2, b3);
                }
            }
            mma16816(Cs[0], ah[0][0], ah[0][1], ah[0][2], ah[0][3], bone, bone);
            mma16816(Cs[1], ah[1][0], ah[1][1], ah[1][2], ah[1][3], bone, bone);
        }

        if (c < 7) {
            char* nbuf = smem + (((c + 1) & 1) ? SM_B1 : SM_B0);
            *(uint4*)(nbuf + db0) = pre0;
            *(uint4*)(nbuf + db1) = pre1;
            __syncthreads();
        }
    }

    // epilogue: sums live in ones-column (col 0, held by q==0 lanes)
    #pragma unroll
    for (int mt = 0; mt < 2; mt++) {
        float s0 = __shfl_sync(0xffffffffu, Cs[mt][0], lane & 28);
        float s1 = __shfl_sync(0xffffffffu, Cs[mt][2], lane & 28);
        float inv0 = 1.f / s0, inv1 = 1.f / s1;
        int rowl = 32 * w + 16 * mt + tg;
        float* o0 = out + ((size_t)(bt * 512 + i0 + rowl)) * 64 + 2 * q;
        float* o1 = o0 + 8 * 64;
        #pragma unroll
        for (int nt = 0; nt < 8; nt++) {
            float v0 = C[mt][nt][0] * inv0, v1 = C[mt][nt][1] * inv0;
            float v2 = C[mt][nt][2] * inv1, v3 = C[mt][nt][3] * inv1;
            v0 = v0 > 0.f ? v0 : __expf(v0) - 1.f;
            v1 = v1 > 0.f ? v1 : __expf(v1) - 1.f;
            v2 = v2 > 0.f ? v2 : __expf(v2) - 1.f;
            v3 = v3 > 0.f ? v3 : __expf(v3) - 1.f;
            *(float2*)&o0[nt * 8] = make_float2(v0, v1);
            *(float2*)&o1[nt * 8] = make_float2(v2, v3);
        }
    }
}

// ---------------------------------------------------------------------------
extern "C" void kernel_launch(void* const* d_in, const int* in_sizes, int n_in,
                              void* d_out, int out_size) {
    const float* h   = (const float*)d_in[0];
    const float* adj = (const float*)d_in[1];
    const float* W   = (const float*)d_in[2];
    const float* a   = (const float*)d_in[3];
    float* out = (float*)d_out;

    cudaFuncSetAttribute(wh_mma_kernel, cudaFuncAttributeMaxDynamicSharedMemorySize,
                         WH_SMEM);
    cudaFuncSetAttribute(att_mma_kernel, cudaFuncAttributeMaxDynamicSharedMemorySize,
                         ATT_SMEM);

    wh_mma_kernel<<<768 + 512, 128, WH_SMEM>>>(h, W, a, adj);
    att_mma_kernel<<<BT * 2, 256, ATT_SMEM>>>(out);
}